// round 3
// baseline (speedup 1.0000x reference)
#include <cuda_runtime.h>
#include <math.h>

// Problem constants (fixed by the reference)
#define Bq   2
#define SEQ  4096
#define HID  1024
#define NHD  16
#define HDIM 64
#define LBLK 64
#define BSZ  64
#define RR   3
#define PENV (-10000.0f)
#define RSD  0.125f   // 1/sqrt(64)

// Head-major scratch for projected q,k,v: [B][NH][S][HD]  (32 MB each)
__device__ float g_q[(size_t)Bq * NHD * SEQ * HDIM];
__device__ float g_k[(size_t)Bq * NHD * SEQ * HDIM];
__device__ float g_v[(size_t)Bq * NHD * SEQ * HDIM];

// ---------------------------------------------------------------------------
// Projection GEMM:  out[b,h,s,d] = sum_e X[b*S+s, e] * W[h*64+d, e] + bias
// C = X (8192 x 1024) @ W^T (1024 x 1024), tiled 64x64x16, 256 threads,
// 4x4 register micro-tile per thread. Output scattered head-major.
// ---------------------------------------------------------------------------
__global__ __launch_bounds__(256) void proj_kernel(
    const float* __restrict__ X, const float* __restrict__ W,
    const float* __restrict__ bias, int which)
{
    __shared__ float As[16][66];
    __shared__ float Bs[16][66];

    float* out = (which == 0) ? g_q : (which == 1) ? g_k : g_v;

    const int t  = threadIdx.x;
    const int tx = t & 15;
    const int ty = t >> 4;
    const int row0 = blockIdx.x * 64;   // row in flattened (B*S)
    const int col0 = blockIdx.y * 64;   // output feature

    const int lm = t >> 2;          // 0..63 : tile row loaded by this thread
    const int lk = (t & 3) * 4;     // 0,4,8,12 : k-offset (float4)

    float c[4][4];
#pragma unroll
    for (int i = 0; i < 4; i++)
#pragma unroll
        for (int j = 0; j < 4; j++) c[i][j] = 0.f;

    for (int k0 = 0; k0 < HID; k0 += 16) {
        float4 av = *(const float4*)(X + (size_t)(row0 + lm) * HID + k0 + lk);
        float4 bv = *(const float4*)(W + (size_t)(col0 + lm) * HID + k0 + lk);
        As[lk + 0][lm] = av.x; As[lk + 1][lm] = av.y;
        As[lk + 2][lm] = av.z; As[lk + 3][lm] = av.w;
        Bs[lk + 0][lm] = bv.x; Bs[lk + 1][lm] = bv.y;
        Bs[lk + 2][lm] = bv.z; Bs[lk + 3][lm] = bv.w;
        __syncthreads();

#pragma unroll
        for (int k = 0; k < 16; k++) {
            float a[4], b[4];
#pragma unroll
            for (int i = 0; i < 4; i++) a[i] = As[k][ty * 4 + i];
#pragma unroll
            for (int j = 0; j < 4; j++) b[j] = Bs[k][tx * 4 + j];
#pragma unroll
            for (int i = 0; i < 4; i++)
#pragma unroll
                for (int j = 0; j < 4; j++) c[i][j] += a[i] * b[j];
        }
        __syncthreads();
    }

#pragma unroll
    for (int i = 0; i < 4; i++) {
        int r  = row0 + ty * 4 + i;
        int bb = r >> 12;              // / SEQ
        int s  = r & (SEQ - 1);
#pragma unroll
        for (int j = 0; j < 4; j++) {
            int o = col0 + tx * 4 + j;
            int h = o >> 6;
            int d = o & 63;
            out[(((size_t)(bb * NHD + h)) * SEQ + s) * HDIM + d] = c[i][j] + bias[o];
        }
    }
}

// ---------------------------------------------------------------------------
// Unified block-sparse flash attention.
// One CTA per (b, h, row-block l).  Key-block list:
//   l==0 or l==L-1 : all 64 blocks (full attention)
//   l==1           : {0,1,2,L-1} + rand[h][0][0..2]
//   l==L-2         : {0,L-3,L-2,L-1} + rand[h][L-3][0..2]
//   else           : {0, l-1, l, l+1, L-1} + rand[h][l-1][0..2]
// Online softmax over the union (order-invariant, lists are duplicate-free).
// Masking: per-key additive penalty (1-mask_k)*PEN + final from_mask multiply
// (identical to the reference for mask == 1, which this problem uses).
// ---------------------------------------------------------------------------
__global__ __launch_bounds__(256) void attn_kernel(
    const float* __restrict__ mask, const int* __restrict__ rand_attn,
    float* __restrict__ out)
{
    extern __shared__ float smem[];
    float* qs  = smem;                 // [64][65]  q tile, row-major
    float* kps = smem + 64 * 65;       // [64][65]  K tile, then reused for P
    float* vs  = smem + 2 * 64 * 65;   // [64][64]  V tile, row-major

    __shared__ int   s_list[64];
    __shared__ int   s_nkb;
    __shared__ float s_pen[64];

    const int t  = threadIdx.x;
    const int tx = t & 15;
    const int ty = t >> 4;

    const int bid = blockIdx.x;
    const int l   = bid & 63;
    const int h   = (bid >> 6) & 15;
    const int b   = bid >> 10;

    const float* qh = g_q + ((size_t)(b * NHD + h)) * SEQ * HDIM;
    const float* kh = g_k + ((size_t)(b * NHD + h)) * SEQ * HDIM;
    const float* vh = g_v + ((size_t)(b * NHD + h)) * SEQ * HDIM;

    // Load q tile (row-major, pitch 65)
#pragma unroll
    for (int rr = 0; rr < 4; rr++) {
        int j  = (t >> 4) + rr * 16;
        int d0 = (t & 15) * 4;
        float4 v4 = *(const float4*)(qh + (size_t)(l * BSZ + j) * HDIM + d0);
        float* p = qs + j * 65 + d0;
        p[0] = v4.x; p[1] = v4.y; p[2] = v4.z; p[3] = v4.w;
    }

    // Build key-block list
    if (t == 0) {
        int n = 0;
        if (l == 0 || l == LBLK - 1) {
            for (int j = 0; j < LBLK; j++) s_list[j] = j;
            n = LBLK;
        } else {
            s_list[n++] = 0;
            if (l == 1) {
                s_list[n++] = 1; s_list[n++] = 2; s_list[n++] = LBLK - 1;
            } else if (l == LBLK - 2) {
                s_list[n++] = LBLK - 3; s_list[n++] = LBLK - 2; s_list[n++] = LBLK - 1;
            } else {
                s_list[n++] = l - 1; s_list[n++] = l; s_list[n++] = l + 1;
                s_list[n++] = LBLK - 1;
            }
            const int* ra = rand_attn + ((size_t)h * (LBLK - 2) + (l - 1)) * RR;
            s_list[n++] = ra[0]; s_list[n++] = ra[1]; s_list[n++] = ra[2];
            s_nkb = n;
        }
        if (l == 0 || l == LBLK - 1) s_nkb = LBLK;
    }
    __syncthreads();
    const int nkb = s_nkb;

    float m_i[4], l_i[4], ctx[4][4];
#pragma unroll
    for (int i = 0; i < 4; i++) {
        m_i[i] = -1e30f; l_i[i] = 0.f;
#pragma unroll
        for (int j = 0; j < 4; j++) ctx[i][j] = 0.f;
    }

    for (int kb = 0; kb < nkb; kb++) {
        const int jb = s_list[kb];

        // Load K (pitch 65) and V (pitch 64) tiles + key mask penalties
#pragma unroll
        for (int rr = 0; rr < 4; rr++) {
            int j  = (t >> 4) + rr * 16;
            int d0 = (t & 15) * 4;
            float4 k4 = *(const float4*)(kh + (size_t)(jb * BSZ + j) * HDIM + d0);
            float* p = kps + j * 65 + d0;
            p[0] = k4.x; p[1] = k4.y; p[2] = k4.z; p[3] = k4.w;
            float4 v4 = *(const float4*)(vh + (size_t)(jb * BSZ + j) * HDIM + d0);
            *(float4*)(vs + j * 64 + d0) = v4;
        }
        if (t < 64)
            s_pen[t] = (1.0f - mask[(size_t)b * SEQ + jb * BSZ + t]) * PENV;
        __syncthreads();

        // S = q @ k^T  (4x4 per thread)
        float sa[4][4];
#pragma unroll
        for (int i = 0; i < 4; i++)
#pragma unroll
            for (int j = 0; j < 4; j++) sa[i][j] = 0.f;

#pragma unroll 16
        for (int d = 0; d < 64; d++) {
            float a[4], bb2[4];
#pragma unroll
            for (int i = 0; i < 4; i++) a[i]   = qs[(ty * 4 + i) * 65 + d];
#pragma unroll
            for (int j = 0; j < 4; j++) bb2[j] = kps[(tx * 4 + j) * 65 + d];
#pragma unroll
            for (int i = 0; i < 4; i++)
#pragma unroll
                for (int j = 0; j < 4; j++) sa[i][j] += a[i] * bb2[j];
        }

        float pen4[4];
#pragma unroll
        for (int j = 0; j < 4; j++) pen4[j] = s_pen[tx * 4 + j];
#pragma unroll
        for (int i = 0; i < 4; i++)
#pragma unroll
            for (int j = 0; j < 4; j++) sa[i][j] = sa[i][j] * RSD + pen4[j];

        // Online softmax update (row reductions across the 16 tx lanes)
#pragma unroll
        for (int i = 0; i < 4; i++) {
            float rmax = fmaxf(fmaxf(sa[i][0], sa[i][1]), fmaxf(sa[i][2], sa[i][3]));
#pragma unroll
            for (int off = 8; off > 0; off >>= 1)
                rmax = fmaxf(rmax, __shfl_xor_sync(0xffffffffu, rmax, off));
            float mnew = fmaxf(m_i[i], rmax);
            float corr = __expf(m_i[i] - mnew);
            m_i[i] = mnew;
            float ps = 0.f;
#pragma unroll
            for (int j = 0; j < 4; j++) {
                sa[i][j] = __expf(sa[i][j] - mnew);
                ps += sa[i][j];
            }
#pragma unroll
            for (int off = 8; off > 0; off >>= 1)
                ps += __shfl_xor_sync(0xffffffffu, ps, off);
            l_i[i] = l_i[i] * corr + ps;
#pragma unroll
            for (int j = 0; j < 4; j++) ctx[i][j] *= corr;
        }

        __syncthreads();   // everyone done reading K from kps
#pragma unroll
        for (int i = 0; i < 4; i++)
#pragma unroll
            for (int j = 0; j < 4; j++)
                kps[(ty * 4 + i) * 65 + tx * 4 + j] = sa[i][j];
        __syncthreads();

        // ctx += P @ V
#pragma unroll 16
        for (int j = 0; j < 64; j++) {
            float pr[4], vv[4];
#pragma unroll
            for (int i = 0; i < 4; i++)  pr[i]  = kps[(ty * 4 + i) * 65 + j];
#pragma unroll
            for (int jj = 0; jj < 4; jj++) vv[jj] = vs[j * 64 + tx * 4 + jj];
#pragma unroll
            for (int i = 0; i < 4; i++)
#pragma unroll
                for (int jj = 0; jj < 4; jj++) ctx[i][jj] += pr[i] * vv[jj];
        }
        __syncthreads();   // before next iteration overwrites kps / vs
    }

    // Normalize, apply from_mask, write (B, S, NH*HD)
#pragma unroll
    for (int i = 0; i < 4; i++) {
        int s = l * BSZ + ty * 4 + i;
        float fm  = mask[(size_t)b * SEQ + s];
        float inv = fm / l_i[i];
#pragma unroll
        for (int j = 0; j < 4; j++)
            out[((size_t)b * SEQ + s) * HID + h * HDIM + tx * 4 + j] = ctx[i][j] * inv;
    }
}

// ---------------------------------------------------------------------------
// Launch
// ---------------------------------------------------------------------------
extern "C" void kernel_launch(void* const* d_in, const int* in_sizes, int n_in,
                              void* d_out, int out_size)
{
    const float* Q    = (const float*)d_in[0];
    const float* K    = (const float*)d_in[1];
    const float* V    = (const float*)d_in[2];
    const float* mask = (const float*)d_in[3];
    const float* Wq   = (const float*)d_in[4];
    const float* bq   = (const float*)d_in[5];
    const float* Wk   = (const float*)d_in[6];
    const float* bk   = (const float*)d_in[7];
    const float* Wv   = (const float*)d_in[8];
    const float* bv   = (const float*)d_in[9];
    const int*   ra   = (const int*)d_in[10];
    float* out = (float*)d_out;

    (void)in_sizes; (void)n_in; (void)out_size;

    // 49,664 B dynamic smem > 48 KB default -> opt in (idempotent, capture-safe)
    static const int attn_smem = (2 * 64 * 65 + 64 * 64) * (int)sizeof(float);
    cudaFuncSetAttribute(attn_kernel,
                         cudaFuncAttributeMaxDynamicSharedMemorySize, attn_smem);

    dim3 gproj((Bq * SEQ) / 64, HID / 64);   // (128, 16)
    proj_kernel<<<gproj, 256>>>(Q, Wq, bq, 0);
    proj_kernel<<<gproj, 256>>>(K, Wk, bk, 1);
    proj_kernel<<<gproj, 256>>>(V, Wv, bv, 2);

    attn_kernel<<<Bq * NHD * LBLK, 256, attn_smem>>>(mask, ra, out);
}

// round 5
// speedup vs baseline: 1.0015x; 1.0015x over previous
#include <cuda_runtime.h>
#include <math.h>

// Problem constants (fixed by the reference)
#define Bq   2
#define SEQ  4096
#define HID  1024
#define NHD  16
#define HDIM 64
#define LBLK 64
#define BSZ  64
#define RR   3
#define PENV (-10000.0f)
#define RSD  0.125f   // 1/sqrt(64)

// Head-major scratch for projected q,k,v: [B][NH][S][HD]  (32 MB each)
__device__ float g_q[(size_t)Bq * NHD * SEQ * HDIM];
__device__ float g_k[(size_t)Bq * NHD * SEQ * HDIM];
__device__ float g_v[(size_t)Bq * NHD * SEQ * HDIM];

// ---------------------------------------------------------------------------
// Projection GEMM:  out[b,h,s,d] = sum_e X[b*S+s, e] * W[h*64+d, e] + bias
// C = X (8192 x 1024) @ W^T (1024 x 1024), tiled 64x64x16, 256 threads,
// 4x4 register micro-tile per thread. Output scattered head-major.
// ---------------------------------------------------------------------------
__global__ __launch_bounds__(256) void proj_kernel(
    const float* __restrict__ X, const float* __restrict__ W,
    const float* __restrict__ bias, int which)
{
    __shared__ float As[16][66];
    __shared__ float Bs[16][66];

    float* out = (which == 0) ? g_q : (which == 1) ? g_k : g_v;

    const int t  = threadIdx.x;
    const int tx = t & 15;
    const int ty = t >> 4;
    const int row0 = blockIdx.x * 64;   // row in flattened (B*S)
    const int col0 = blockIdx.y * 64;   // output feature

    const int lm = t >> 2;          // 0..63 : tile row loaded by this thread
    const int lk = (t & 3) * 4;     // 0,4,8,12 : k-offset (float4)

    float c[4][4];
#pragma unroll
    for (int i = 0; i < 4; i++)
#pragma unroll
        for (int j = 0; j < 4; j++) c[i][j] = 0.f;

    for (int k0 = 0; k0 < HID; k0 += 16) {
        float4 av = *(const float4*)(X + (size_t)(row0 + lm) * HID + k0 + lk);
        float4 bv = *(const float4*)(W + (size_t)(col0 + lm) * HID + k0 + lk);
        As[lk + 0][lm] = av.x; As[lk + 1][lm] = av.y;
        As[lk + 2][lm] = av.z; As[lk + 3][lm] = av.w;
        Bs[lk + 0][lm] = bv.x; Bs[lk + 1][lm] = bv.y;
        Bs[lk + 2][lm] = bv.z; Bs[lk + 3][lm] = bv.w;
        __syncthreads();

#pragma unroll
        for (int k = 0; k < 16; k++) {
            float a[4], b[4];
#pragma unroll
            for (int i = 0; i < 4; i++) a[i] = As[k][ty * 4 + i];
#pragma unroll
            for (int j = 0; j < 4; j++) b[j] = Bs[k][tx * 4 + j];
#pragma unroll
            for (int i = 0; i < 4; i++)
#pragma unroll
                for (int j = 0; j < 4; j++) c[i][j] += a[i] * b[j];
        }
        __syncthreads();
    }

#pragma unroll
    for (int i = 0; i < 4; i++) {
        int r  = row0 + ty * 4 + i;
        int bb = r >> 12;              // / SEQ
        int s  = r & (SEQ - 1);
#pragma unroll
        for (int j = 0; j < 4; j++) {
            int o = col0 + tx * 4 + j;
            int h = o >> 6;
            int d = o & 63;
            out[(((size_t)(bb * NHD + h)) * SEQ + s) * HDIM + d] = c[i][j] + bias[o];
        }
    }
}

// ---------------------------------------------------------------------------
// Unified block-sparse flash attention.
// One CTA per (b, h, row-block l).  Key-block list:
//   l==0 or l==L-1 : all 64 blocks (full attention)
//   l==1           : {0,1,2,L-1} + rand[h][0][0..2]
//   l==L-2         : {0,L-3,L-2,L-1} + rand[h][L-3][0..2]
//   else           : {0, l-1, l, l+1, L-1} + rand[h][l-1][0..2]
// Online softmax over the union (order-invariant, lists are duplicate-free).
// Masking: per-key additive penalty (1-mask_k)*PEN + final from_mask multiply
// (identical to the reference for mask == 1, which this problem uses).
// ---------------------------------------------------------------------------
__global__ __launch_bounds__(256) void attn_kernel(
    const float* __restrict__ mask, const int* __restrict__ rand_attn,
    float* __restrict__ out)
{
    extern __shared__ float smem[];
    float* qs  = smem;                 // [64][65]  q tile, row-major
    float* kps = smem + 64 * 65;       // [64][65]  K tile, then reused for P
    float* vs  = smem + 2 * 64 * 65;   // [64][64]  V tile, row-major

    __shared__ int   s_list[64];
    __shared__ int   s_nkb;
    __shared__ float s_pen[64];

    const int t  = threadIdx.x;
    const int tx = t & 15;
    const int ty = t >> 4;

    const int bid = blockIdx.x;
    const int l   = bid & 63;
    const int h   = (bid >> 6) & 15;
    const int b   = bid >> 10;

    const float* qh = g_q + ((size_t)(b * NHD + h)) * SEQ * HDIM;
    const float* kh = g_k + ((size_t)(b * NHD + h)) * SEQ * HDIM;
    const float* vh = g_v + ((size_t)(b * NHD + h)) * SEQ * HDIM;

    // Load q tile (row-major, pitch 65)
#pragma unroll
    for (int rr = 0; rr < 4; rr++) {
        int j  = (t >> 4) + rr * 16;
        int d0 = (t & 15) * 4;
        float4 v4 = *(const float4*)(qh + (size_t)(l * BSZ + j) * HDIM + d0);
        float* p = qs + j * 65 + d0;
        p[0] = v4.x; p[1] = v4.y; p[2] = v4.z; p[3] = v4.w;
    }

    // Build key-block list
    if (t == 0) {
        int n = 0;
        if (l == 0 || l == LBLK - 1) {
            for (int j = 0; j < LBLK; j++) s_list[j] = j;
            n = LBLK;
        } else {
            s_list[n++] = 0;
            if (l == 1) {
                s_list[n++] = 1; s_list[n++] = 2; s_list[n++] = LBLK - 1;
            } else if (l == LBLK - 2) {
                s_list[n++] = LBLK - 3; s_list[n++] = LBLK - 2; s_list[n++] = LBLK - 1;
            } else {
                s_list[n++] = l - 1; s_list[n++] = l; s_list[n++] = l + 1;
                s_list[n++] = LBLK - 1;
            }
            const int* ra = rand_attn + ((size_t)h * (LBLK - 2) + (l - 1)) * RR;
            s_list[n++] = ra[0]; s_list[n++] = ra[1]; s_list[n++] = ra[2];
            s_nkb = n;
        }
        if (l == 0 || l == LBLK - 1) s_nkb = LBLK;
    }
    __syncthreads();
    const int nkb = s_nkb;

    float m_i[4], l_i[4], ctx[4][4];
#pragma unroll
    for (int i = 0; i < 4; i++) {
        m_i[i] = -1e30f; l_i[i] = 0.f;
#pragma unroll
        for (int j = 0; j < 4; j++) ctx[i][j] = 0.f;
    }

    for (int kb = 0; kb < nkb; kb++) {
        const int jb = s_list[kb];

        // Load K (pitch 65) and V (pitch 64) tiles + key mask penalties
#pragma unroll
        for (int rr = 0; rr < 4; rr++) {
            int j  = (t >> 4) + rr * 16;
            int d0 = (t & 15) * 4;
            float4 k4 = *(const float4*)(kh + (size_t)(jb * BSZ + j) * HDIM + d0);
            float* p = kps + j * 65 + d0;
            p[0] = k4.x; p[1] = k4.y; p[2] = k4.z; p[3] = k4.w;
            float4 v4 = *(const float4*)(vh + (size_t)(jb * BSZ + j) * HDIM + d0);
            *(float4*)(vs + j * 64 + d0) = v4;
        }
        if (t < 64)
            s_pen[t] = (1.0f - mask[(size_t)b * SEQ + jb * BSZ + t]) * PENV;
        __syncthreads();

        // S = q @ k^T  (4x4 per thread)
        float sa[4][4];
#pragma unroll
        for (int i = 0; i < 4; i++)
#pragma unroll
            for (int j = 0; j < 4; j++) sa[i][j] = 0.f;

#pragma unroll 16
        for (int d = 0; d < 64; d++) {
            float a[4], bb2[4];
#pragma unroll
            for (int i = 0; i < 4; i++) a[i]   = qs[(ty * 4 + i) * 65 + d];
#pragma unroll
            for (int j = 0; j < 4; j++) bb2[j] = kps[(tx * 4 + j) * 65 + d];
#pragma unroll
            for (int i = 0; i < 4; i++)
#pragma unroll
                for (int j = 0; j < 4; j++) sa[i][j] += a[i] * bb2[j];
        }

        float pen4[4];
#pragma unroll
        for (int j = 0; j < 4; j++) pen4[j] = s_pen[tx * 4 + j];
#pragma unroll
        for (int i = 0; i < 4; i++)
#pragma unroll
            for (int j = 0; j < 4; j++) sa[i][j] = sa[i][j] * RSD + pen4[j];

        // Online softmax update (row reductions across the 16 tx lanes)
#pragma unroll
        for (int i = 0; i < 4; i++) {
            float rmax = fmaxf(fmaxf(sa[i][0], sa[i][1]), fmaxf(sa[i][2], sa[i][3]));
#pragma unroll
            for (int off = 8; off > 0; off >>= 1)
                rmax = fmaxf(rmax, __shfl_xor_sync(0xffffffffu, rmax, off));
            float mnew = fmaxf(m_i[i], rmax);
            float corr = __expf(m_i[i] - mnew);
            m_i[i] = mnew;
            float ps = 0.f;
#pragma unroll
            for (int j = 0; j < 4; j++) {
                sa[i][j] = __expf(sa[i][j] - mnew);
                ps += sa[i][j];
            }
#pragma unroll
            for (int off = 8; off > 0; off >>= 1)
                ps += __shfl_xor_sync(0xffffffffu, ps, off);
            l_i[i] = l_i[i] * corr + ps;
#pragma unroll
            for (int j = 0; j < 4; j++) ctx[i][j] *= corr;
        }

        __syncthreads();   // everyone done reading K from kps
#pragma unroll
        for (int i = 0; i < 4; i++)
#pragma unroll
            for (int j = 0; j < 4; j++)
                kps[(ty * 4 + i) * 65 + tx * 4 + j] = sa[i][j];
        __syncthreads();

        // ctx += P @ V
#pragma unroll 16
        for (int j = 0; j < 64; j++) {
            float pr[4], vv[4];
#pragma unroll
            for (int i = 0; i < 4; i++)  pr[i]  = kps[(ty * 4 + i) * 65 + j];
#pragma unroll
            for (int jj = 0; jj < 4; jj++) vv[jj] = vs[j * 64 + tx * 4 + jj];
#pragma unroll
            for (int i = 0; i < 4; i++)
#pragma unroll
                for (int jj = 0; jj < 4; jj++) ctx[i][jj] += pr[i] * vv[jj];
        }
        __syncthreads();   // before next iteration overwrites kps / vs
    }

    // Normalize, apply from_mask, write (B, S, NH*HD)
#pragma unroll
    for (int i = 0; i < 4; i++) {
        int s = l * BSZ + ty * 4 + i;
        float fm  = mask[(size_t)b * SEQ + s];
        float inv = fm / l_i[i];
#pragma unroll
        for (int j = 0; j < 4; j++)
            out[((size_t)b * SEQ + s) * HID + h * HDIM + tx * 4 + j] = ctx[i][j] * inv;
    }
}

// ---------------------------------------------------------------------------
// Launch
// ---------------------------------------------------------------------------
extern "C" void kernel_launch(void* const* d_in, const int* in_sizes, int n_in,
                              void* d_out, int out_size)
{
    const float* Q    = (const float*)d_in[0];
    const float* K    = (const float*)d_in[1];
    const float* V    = (const float*)d_in[2];
    const float* mask = (const float*)d_in[3];
    const float* Wq   = (const float*)d_in[4];
    const float* bq   = (const float*)d_in[5];
    const float* Wk   = (const float*)d_in[6];
    const float* bk   = (const float*)d_in[7];
    const float* Wv   = (const float*)d_in[8];
    const float* bv   = (const float*)d_in[9];
    const int*   ra   = (const int*)d_in[10];
    float* out = (float*)d_out;

    (void)in_sizes; (void)n_in; (void)out_size;

    // 49,664 B dynamic smem > 48 KB default -> opt in (idempotent, capture-safe)
    static const int attn_smem = (2 * 64 * 65 + 64 * 64) * (int)sizeof(float);
    cudaFuncSetAttribute(attn_kernel,
                         cudaFuncAttributeMaxDynamicSharedMemorySize, attn_smem);

    dim3 gproj((Bq * SEQ) / 64, HID / 64);   // (128, 16)
    proj_kernel<<<gproj, 256>>>(Q, Wq, bq, 0);
    proj_kernel<<<gproj, 256>>>(K, Wk, bk, 1);
    proj_kernel<<<gproj, 256>>>(V, Wv, bv, 2);

    attn_kernel<<<Bq * NHD * LBLK, 256, attn_smem>>>(mask, ra, out);
}

// round 6
// speedup vs baseline: 1.0016x; 1.0001x over previous
#include <cuda_runtime.h>
#include <math.h>

// Problem constants (fixed by the reference)
#define Bq   2
#define SEQ  4096
#define HID  1024
#define NHD  16
#define HDIM 64
#define LBLK 64
#define BSZ  64
#define RR   3
#define PENV (-10000.0f)
#define RSD  0.125f   // 1/sqrt(64)

// Head-major scratch for projected q,k,v: [B][NH][S][HD]  (32 MB each)
__device__ float g_q[(size_t)Bq * NHD * SEQ * HDIM];
__device__ float g_k[(size_t)Bq * NHD * SEQ * HDIM];
__device__ float g_v[(size_t)Bq * NHD * SEQ * HDIM];

// ---------------------------------------------------------------------------
// Projection GEMM:  out[b,h,s,d] = sum_e X[b*S+s, e] * W[h*64+d, e] + bias
// C = X (8192 x 1024) @ W^T (1024 x 1024), tiled 64x64x16, 256 threads,
// 4x4 register micro-tile per thread. Output scattered head-major.
// ---------------------------------------------------------------------------
__global__ __launch_bounds__(256) void proj_kernel(
    const float* __restrict__ X, const float* __restrict__ W,
    const float* __restrict__ bias, int which)
{
    __shared__ float As[16][66];
    __shared__ float Bs[16][66];

    float* out = (which == 0) ? g_q : (which == 1) ? g_k : g_v;

    const int t  = threadIdx.x;
    const int tx = t & 15;
    const int ty = t >> 4;
    const int row0 = blockIdx.x * 64;   // row in flattened (B*S)
    const int col0 = blockIdx.y * 64;   // output feature

    const int lm = t >> 2;          // 0..63 : tile row loaded by this thread
    const int lk = (t & 3) * 4;     // 0,4,8,12 : k-offset (float4)

    float c[4][4];
#pragma unroll
    for (int i = 0; i < 4; i++)
#pragma unroll
        for (int j = 0; j < 4; j++) c[i][j] = 0.f;

    for (int k0 = 0; k0 < HID; k0 += 16) {
        float4 av = *(const float4*)(X + (size_t)(row0 + lm) * HID + k0 + lk);
        float4 bv = *(const float4*)(W + (size_t)(col0 + lm) * HID + k0 + lk);
        As[lk + 0][lm] = av.x; As[lk + 1][lm] = av.y;
        As[lk + 2][lm] = av.z; As[lk + 3][lm] = av.w;
        Bs[lk + 0][lm] = bv.x; Bs[lk + 1][lm] = bv.y;
        Bs[lk + 2][lm] = bv.z; Bs[lk + 3][lm] = bv.w;
        __syncthreads();

#pragma unroll
        for (int k = 0; k < 16; k++) {
            float a[4], b[4];
#pragma unroll
            for (int i = 0; i < 4; i++) a[i] = As[k][ty * 4 + i];
#pragma unroll
            for (int j = 0; j < 4; j++) b[j] = Bs[k][tx * 4 + j];
#pragma unroll
            for (int i = 0; i < 4; i++)
#pragma unroll
                for (int j = 0; j < 4; j++) c[i][j] += a[i] * b[j];
        }
        __syncthreads();
    }

#pragma unroll
    for (int i = 0; i < 4; i++) {
        int r  = row0 + ty * 4 + i;
        int bb = r >> 12;              // / SEQ
        int s  = r & (SEQ - 1);
#pragma unroll
        for (int j = 0; j < 4; j++) {
            int o = col0 + tx * 4 + j;
            int h = o >> 6;
            int d = o & 63;
            out[(((size_t)(bb * NHD + h)) * SEQ + s) * HDIM + d] = c[i][j] + bias[o];
        }
    }
}

// ---------------------------------------------------------------------------
// Unified block-sparse flash attention.
// One CTA per (b, h, row-block l).  Key-block list:
//   l==0 or l==L-1 : all 64 blocks (full attention)
//   l==1           : {0,1,2,L-1} + rand[h][0][0..2]
//   l==L-2         : {0,L-3,L-2,L-1} + rand[h][L-3][0..2]
//   else           : {0, l-1, l, l+1, L-1} + rand[h][l-1][0..2]
// Online softmax over the union (order-invariant, lists are duplicate-free).
// Masking: per-key additive penalty (1-mask_k)*PEN + final from_mask multiply
// (identical to the reference for mask == 1, which this problem uses).
// ---------------------------------------------------------------------------
__global__ __launch_bounds__(256) void attn_kernel(
    const float* __restrict__ mask, const int* __restrict__ rand_attn,
    float* __restrict__ out)
{
    extern __shared__ float smem[];
    float* qs  = smem;                 // [64][65]  q tile, row-major
    float* kps = smem + 64 * 65;       // [64][65]  K tile, then reused for P
    float* vs  = smem + 2 * 64 * 65;   // [64][64]  V tile, row-major

    __shared__ int   s_list[64];
    __shared__ int   s_nkb;
    __shared__ float s_pen[64];

    const int t  = threadIdx.x;
    const int tx = t & 15;
    const int ty = t >> 4;

    const int bid = blockIdx.x;
    const int l   = bid & 63;
    const int h   = (bid >> 6) & 15;
    const int b   = bid >> 10;

    const float* qh = g_q + ((size_t)(b * NHD + h)) * SEQ * HDIM;
    const float* kh = g_k + ((size_t)(b * NHD + h)) * SEQ * HDIM;
    const float* vh = g_v + ((size_t)(b * NHD + h)) * SEQ * HDIM;

    // Load q tile (row-major, pitch 65)
#pragma unroll
    for (int rr = 0; rr < 4; rr++) {
        int j  = (t >> 4) + rr * 16;
        int d0 = (t & 15) * 4;
        float4 v4 = *(const float4*)(qh + (size_t)(l * BSZ + j) * HDIM + d0);
        float* p = qs + j * 65 + d0;
        p[0] = v4.x; p[1] = v4.y; p[2] = v4.z; p[3] = v4.w;
    }

    // Build key-block list
    if (t == 0) {
        int n = 0;
        if (l == 0 || l == LBLK - 1) {
            for (int j = 0; j < LBLK; j++) s_list[j] = j;
            n = LBLK;
        } else {
            s_list[n++] = 0;
            if (l == 1) {
                s_list[n++] = 1; s_list[n++] = 2; s_list[n++] = LBLK - 1;
            } else if (l == LBLK - 2) {
                s_list[n++] = LBLK - 3; s_list[n++] = LBLK - 2; s_list[n++] = LBLK - 1;
            } else {
                s_list[n++] = l - 1; s_list[n++] = l; s_list[n++] = l + 1;
                s_list[n++] = LBLK - 1;
            }
            const int* ra = rand_attn + ((size_t)h * (LBLK - 2) + (l - 1)) * RR;
            s_list[n++] = ra[0]; s_list[n++] = ra[1]; s_list[n++] = ra[2];
            s_nkb = n;
        }
        if (l == 0 || l == LBLK - 1) s_nkb = LBLK;
    }
    __syncthreads();
    const int nkb = s_nkb;

    float m_i[4], l_i[4], ctx[4][4];
#pragma unroll
    for (int i = 0; i < 4; i++) {
        m_i[i] = -1e30f; l_i[i] = 0.f;
#pragma unroll
        for (int j = 0; j < 4; j++) ctx[i][j] = 0.f;
    }

    for (int kb = 0; kb < nkb; kb++) {
        const int jb = s_list[kb];

        // Load K (pitch 65) and V (pitch 64) tiles + key mask penalties
#pragma unroll
        for (int rr = 0; rr < 4; rr++) {
            int j  = (t >> 4) + rr * 16;
            int d0 = (t & 15) * 4;
            float4 k4 = *(const float4*)(kh + (size_t)(jb * BSZ + j) * HDIM + d0);
            float* p = kps + j * 65 + d0;
            p[0] = k4.x; p[1] = k4.y; p[2] = k4.z; p[3] = k4.w;
            float4 v4 = *(const float4*)(vh + (size_t)(jb * BSZ + j) * HDIM + d0);
            *(float4*)(vs + j * 64 + d0) = v4;
        }
        if (t < 64)
            s_pen[t] = (1.0f - mask[(size_t)b * SEQ + jb * BSZ + t]) * PENV;
        __syncthreads();

        // S = q @ k^T  (4x4 per thread)
        float sa[4][4];
#pragma unroll
        for (int i = 0; i < 4; i++)
#pragma unroll
            for (int j = 0; j < 4; j++) sa[i][j] = 0.f;

#pragma unroll 16
        for (int d = 0; d < 64; d++) {
            float a[4], bb2[4];
#pragma unroll
            for (int i = 0; i < 4; i++) a[i]   = qs[(ty * 4 + i) * 65 + d];
#pragma unroll
            for (int j = 0; j < 4; j++) bb2[j] = kps[(tx * 4 + j) * 65 + d];
#pragma unroll
            for (int i = 0; i < 4; i++)
#pragma unroll
                for (int j = 0; j < 4; j++) sa[i][j] += a[i] * bb2[j];
        }

        float pen4[4];
#pragma unroll
        for (int j = 0; j < 4; j++) pen4[j] = s_pen[tx * 4 + j];
#pragma unroll
        for (int i = 0; i < 4; i++)
#pragma unroll
            for (int j = 0; j < 4; j++) sa[i][j] = sa[i][j] * RSD + pen4[j];

        // Online softmax update (row reductions across the 16 tx lanes)
#pragma unroll
        for (int i = 0; i < 4; i++) {
            float rmax = fmaxf(fmaxf(sa[i][0], sa[i][1]), fmaxf(sa[i][2], sa[i][3]));
#pragma unroll
            for (int off = 8; off > 0; off >>= 1)
                rmax = fmaxf(rmax, __shfl_xor_sync(0xffffffffu, rmax, off));
            float mnew = fmaxf(m_i[i], rmax);
            float corr = __expf(m_i[i] - mnew);
            m_i[i] = mnew;
            float ps = 0.f;
#pragma unroll
            for (int j = 0; j < 4; j++) {
                sa[i][j] = __expf(sa[i][j] - mnew);
                ps += sa[i][j];
            }
#pragma unroll
            for (int off = 8; off > 0; off >>= 1)
                ps += __shfl_xor_sync(0xffffffffu, ps, off);
            l_i[i] = l_i[i] * corr + ps;
#pragma unroll
            for (int j = 0; j < 4; j++) ctx[i][j] *= corr;
        }

        __syncthreads();   // everyone done reading K from kps
#pragma unroll
        for (int i = 0; i < 4; i++)
#pragma unroll
            for (int j = 0; j < 4; j++)
                kps[(ty * 4 + i) * 65 + tx * 4 + j] = sa[i][j];
        __syncthreads();

        // ctx += P @ V
#pragma unroll 16
        for (int j = 0; j < 64; j++) {
            float pr[4], vv[4];
#pragma unroll
            for (int i = 0; i < 4; i++)  pr[i]  = kps[(ty * 4 + i) * 65 + j];
#pragma unroll
            for (int jj = 0; jj < 4; jj++) vv[jj] = vs[j * 64 + tx * 4 + jj];
#pragma unroll
            for (int i = 0; i < 4; i++)
#pragma unroll
                for (int jj = 0; jj < 4; jj++) ctx[i][jj] += pr[i] * vv[jj];
        }
        __syncthreads();   // before next iteration overwrites kps / vs
    }

    // Normalize, apply from_mask, write (B, S, NH*HD)
#pragma unroll
    for (int i = 0; i < 4; i++) {
        int s = l * BSZ + ty * 4 + i;
        float fm  = mask[(size_t)b * SEQ + s];
        float inv = fm / l_i[i];
#pragma unroll
        for (int j = 0; j < 4; j++)
            out[((size_t)b * SEQ + s) * HID + h * HDIM + tx * 4 + j] = ctx[i][j] * inv;
    }
}

// ---------------------------------------------------------------------------
// Launch
// ---------------------------------------------------------------------------
extern "C" void kernel_launch(void* const* d_in, const int* in_sizes, int n_in,
                              void* d_out, int out_size)
{
    const float* Q    = (const float*)d_in[0];
    const float* K    = (const float*)d_in[1];
    const float* V    = (const float*)d_in[2];
    const float* mask = (const float*)d_in[3];
    const float* Wq   = (const float*)d_in[4];
    const float* bq   = (const float*)d_in[5];
    const float* Wk   = (const float*)d_in[6];
    const float* bk   = (const float*)d_in[7];
    const float* Wv   = (const float*)d_in[8];
    const float* bv   = (const float*)d_in[9];
    const int*   ra   = (const int*)d_in[10];
    float* out = (float*)d_out;

    (void)in_sizes; (void)n_in; (void)out_size;

    // 49,664 B dynamic smem > 48 KB default -> opt in (idempotent, capture-safe)
    static const int attn_smem = (2 * 64 * 65 + 64 * 64) * (int)sizeof(float);
    cudaFuncSetAttribute(attn_kernel,
                         cudaFuncAttributeMaxDynamicSharedMemorySize, attn_smem);

    dim3 gproj((Bq * SEQ) / 64, HID / 64);   // (128, 16)
    proj_kernel<<<gproj, 256>>>(Q, Wq, bq, 0);
    proj_kernel<<<gproj, 256>>>(K, Wk, bk, 1);
    proj_kernel<<<gproj, 256>>>(V, Wv, bv, 2);

    attn_kernel<<<Bq * NHD * LBLK, 256, attn_smem>>>(mask, ra, out);
}